// round 2
// baseline (speedup 1.0000x reference)
#include <cuda_runtime.h>
#include <cstdint>

typedef unsigned long long ull_t;

// packed f32x2 ops (Blackwell FFMA2 path)
__device__ __forceinline__ void ffma2(ull_t &acc, ull_t a, ull_t b) {
    asm volatile("fma.rn.f32x2 %0, %1, %2, %0;" : "+l"(acc) : "l"(a), "l"(b));
}
__device__ __forceinline__ ull_t add2(ull_t a, ull_t b) {
    ull_t r; asm("add.rn.f32x2 %0, %1, %2;" : "=l"(r) : "l"(a), "l"(b)); return r;
}
__device__ __forceinline__ float hsum2(ull_t v) {
    float lo, hi; asm("mov.b64 {%0,%1}, %2;" : "=f"(lo), "=f"(hi) : "l"(v));
    return lo + hi;
}

__device__ __forceinline__ void cp_async16(uint32_t dst, const void* src, int src_sz) {
    asm volatile("cp.async.cg.shared.global [%0], [%1], 16, %2;"
                 :: "r"(dst), "l"(src), "r"(src_sz));
}
__device__ __forceinline__ void cp_commit() {
    asm volatile("cp.async.commit_group;");
}
__device__ __forceinline__ void cp_wait1() {
    asm volatile("cp.async.wait_group 1;" ::: "memory");
}

// H=64, D=32 fixed. Block = 256 threads = 2 batches; within a batch, channel j is
// split across 2 adjacent lanes (half-dot each, shfl.xor(1) reduce) -> 8 warps/CTA
// = 2 warps per SMSP for latency hiding.
__global__ void __launch_bounds__(256, 1)
ctrnn_scan_kernel(const float* __restrict__ x,
                  const float* __restrict__ W_in,
                  const float* __restrict__ b_in,
                  const float* __restrict__ W_hh,
                  const float* __restrict__ b_hh,
                  float* __restrict__ out,
                  int B, int T)
{
    constexpr int H  = 64;
    constexpr int D  = 32;
    constexpr int CH = 32;   // timesteps per x-staging chunk

    const int tid  = threadIdx.x;
    const int sb   = tid >> 7;       // batch slot within block (0/1)
    const int r    = tid & 127;      // thread within batch
    const int j    = r >> 1;         // channel 0..63
    const int half = r & 1;          // which half of the dot
    const int b    = blockIdx.x * 2 + sb;
    const bool active = (b < B);
    const int bc   = active ? b : (B - 1);

    __shared__ __align__(16) float hbuf[2][2][H];        // [ping][sb][H]
    __shared__ __align__(16) float xbuf[2][2][CH * D];   // [ping][sb][CH*D]

    // ---- this thread's half-row of weights as packed f32x2 ----
    ull_t wu[16];   // W_hh[j][half*32 .. half*32+31]
    {
        const ulonglong2* wr = reinterpret_cast<const ulonglong2*>(W_hh + j * H + half * 32);
#pragma unroll
        for (int m = 0; m < 8; m++) { ulonglong2 v = wr[m]; wu[2*m] = v.x; wu[2*m+1] = v.y; }
    }
    ull_t iu[8];    // W_in[j][half*16 .. half*16+15]
    {
        const ulonglong2* wr = reinterpret_cast<const ulonglong2*>(W_in + j * D + half * 16);
#pragma unroll
        for (int m = 0; m < 4; m++) { ulonglong2 v = wr[m]; iu[2*m] = v.x; iu[2*m+1] = v.y; }
    }
    const float bias  = b_hh[j] + b_in[j];
    const float alpha = (float)(16.67 / 40.0);
    const float oma   = (float)(1.0 - 16.67 / 40.0);

    if (half == 0) hbuf[0][sb][j] = 0.0f;   // h0 = 0
    float hj = 0.0f;

    const int nchunk = (T + CH - 1) / CH;

    // ---- async x chunk loader: 128 threads/batch copy CH*D*4 = 4KB (2x16B each) ----
    auto issue_chunk = [&](int c, int buf) {
        const size_t base_elem = ((size_t)bc * T + (size_t)c * CH) * D;
        const char* srcb = (const char*)(x + base_elem);
        uint32_t dstb = (uint32_t)__cvta_generic_to_shared(&xbuf[buf][sb][0]);
#pragma unroll
        for (int q = 0; q < 2; q++) {
            int off16 = r + 128 * q;          // 16B-unit index, 256 units per chunk
            int row   = off16 >> 3;           // D*4/16 = 8 units per timestep row
            bool ok   = active && (c * CH + row) < T;
            const void* src = ok ? (const void*)(srcb + (size_t)off16 * 16)
                                 : (const void*)x;
            cp_async16(dstb + off16 * 16, src, ok ? 16 : 0);
        }
        cp_commit();
    };

    issue_chunk(0, 0);
    if (nchunk > 1) issue_chunk(1, 1); else cp_commit();

    int cur = 0;
    const size_t outbase = (size_t)bc * T * H + j;   // used by half==0 only

#define STEP_BODY(tt)                                                              \
    {                                                                              \
        const ulonglong2* hp = reinterpret_cast<const ulonglong2*>(                \
            &hbuf[cur][sb][half * 32]);                                            \
        const ulonglong2* xp = reinterpret_cast<const ulonglong2*>(                \
            &xbuf[xb][sb][(tt) * D + half * 16]);                                  \
        ull_t a0 = 0ull, a1 = 0ull, a2 = 0ull, a3 = 0ull;                          \
        const float leak = hj * oma;                                               \
        _Pragma("unroll")                                                          \
        for (int m = 0; m < 8; m++) {                                              \
            ulonglong2 hv = hp[m];                                                 \
            ffma2((m & 1) ? a1 : a0, wu[2 * m],     hv.x);                         \
            ffma2((m & 1) ? a3 : a2, wu[2 * m + 1], hv.y);                         \
        }                                                                          \
        _Pragma("unroll")                                                          \
        for (int m = 0; m < 4; m++) {                                              \
            ulonglong2 xv = xp[m];                                                 \
            ffma2((m & 1) ? a1 : a0, iu[2 * m],     xv.x);                         \
            ffma2((m & 1) ? a3 : a2, iu[2 * m + 1], xv.y);                         \
        }                                                                          \
        float p   = hsum2(add2(add2(a0, a1), add2(a2, a3)));                       \
        float tot = p + __shfl_xor_sync(0xffffffffu, p, 1);                        \
        float hnew = fmaxf(fmaf(tot + bias, alpha, leak), 0.0f);                   \
        if (half == 0) {                                                           \
            hbuf[cur ^ 1][sb][j] = hnew;                                           \
            if (active) out[obase_c + (size_t)(tt) * H] = hnew;                    \
        }                                                                          \
        hj = hnew;                                                                 \
        cur ^= 1;                                                                  \
        __syncthreads();                                                           \
    }

    for (int c = 0; c < nchunk; c++) {
        cp_wait1();            // chunk c landed (in-order group completion)
        __syncthreads();       // all threads' waits done -> xbuf chunk c visible

        const int xb   = c & 1;
        const int tend = min(CH, T - c * CH);
        const size_t obase_c = outbase + (size_t)c * CH * H;

        if (tend == CH) {
#pragma unroll 4
            for (int tt = 0; tt < CH; tt++) STEP_BODY(tt)
        } else {
            for (int tt = 0; tt < tend; tt++) STEP_BODY(tt)
        }

        if (c + 2 < nchunk) issue_chunk(c + 2, xb); else cp_commit();
    }
#undef STEP_BODY

    // h_last appended after outputs
    if (active && half == 0) out[(size_t)B * T * H + (size_t)b * H + j] = hj;
}

extern "C" void kernel_launch(void* const* d_in, const int* in_sizes, int n_in,
                              void* d_out, int out_size)
{
    const float* x    = (const float*)d_in[0];
    // d_in[1] = seq_lengths: forward-dead (mask only gates gradients)
    const float* W_in = (const float*)d_in[2];
    const float* b_in = (const float*)d_in[3];
    const float* W_hh = (const float*)d_in[4];
    const float* b_hh = (const float*)d_in[5];
    float* out = (float*)d_out;

    const int B = in_sizes[1];
    const int H = in_sizes[5];
    const int D = in_sizes[2] / H;
    const long long T = (long long)in_sizes[0] / ((long long)B * D);

    const int grid = (B + 1) / 2;
    ctrnn_scan_kernel<<<grid, 256>>>(x, W_in, b_in, W_hh, b_hh, out, B, (int)T);
}

// round 3
// speedup vs baseline: 1.1269x; 1.1269x over previous
#include <cuda_runtime.h>
#include <cstdint>

typedef unsigned long long ull_t;

__device__ __forceinline__ void ffma2(ull_t &acc, ull_t a, ull_t b) {
    asm volatile("fma.rn.f32x2 %0, %1, %2, %0;" : "+l"(acc) : "l"(a), "l"(b));
}
__device__ __forceinline__ ull_t add2(ull_t a, ull_t b) {
    ull_t r; asm("add.rn.f32x2 %0, %1, %2;" : "=l"(r) : "l"(a), "l"(b)); return r;
}
__device__ __forceinline__ float hsum2(ull_t v) {
    float lo, hi; asm("mov.b64 {%0,%1}, %2;" : "=f"(lo), "=f"(hi) : "l"(v));
    return lo + hi;
}
__device__ __forceinline__ ull_t pack2(float lo, float hi) {
    ull_t r; asm("mov.b64 %0, {%1, %2};" : "=l"(r) : "f"(lo), "f"(hi)); return r;
}

__device__ __forceinline__ void cp_async16(uint32_t dst, const void* src, int src_sz) {
    asm volatile("cp.async.cg.shared.global [%0], [%1], 16, %2;"
                 :: "r"(dst), "l"(src), "r"(src_sz));
}
__device__ __forceinline__ void cp_commit() {
    asm volatile("cp.async.commit_group;");
}
__device__ __forceinline__ void cp_wait1() {
    asm volatile("cp.async.wait_group 1;" ::: "memory");
}
// per-batch-group barrier: ids 1 and 2, 128 threads each
__device__ __forceinline__ void group_bar(int id) {
    asm volatile("bar.sync %0, 128;" :: "r"(id) : "memory");
}

// H=64, D=32 fixed. Block = 256 threads = 2 INDEPENDENT batch groups of 128
// threads. Within a group: channel j split across 2 adjacent lanes (half-dot
// each, shfl.xor(1) reduce). Warps 0-3 = batch0 (SMSP 0-3), warps 4-7 = batch1
// (SMSP 0-3): each SMSP runs two warps on independent chains with independent
// named barriers -> mutual stall hiding.
__global__ void __launch_bounds__(256, 1)
ctrnn_scan_kernel(const float* __restrict__ x,
                  const float* __restrict__ W_in,
                  const float* __restrict__ b_in,
                  const float* __restrict__ W_hh,
                  const float* __restrict__ b_hh,
                  float* __restrict__ out,
                  int B, int T)
{
    constexpr int H  = 64;
    constexpr int D  = 32;
    constexpr int CH = 32;   // timesteps per x-staging chunk

    const int tid  = threadIdx.x;
    const int sb   = tid >> 7;       // batch group (0/1) == warp>=4
    const int r    = tid & 127;      // thread within group
    const int j    = r >> 1;         // channel 0..63
    const int half = r & 1;          // which half of the dot
    const int barid = sb + 1;        // named barrier per group
    const int b    = blockIdx.x * 2 + sb;
    const bool active = (b < B);
    const int bc   = active ? b : (B - 1);

    __shared__ __align__(16) float hbuf[2][2][H];        // [ping][sb][H]
    __shared__ __align__(16) float xbuf[2][2][CH * D];   // [ping][sb][CH*D]

    // ---- this thread's half-row of weights as packed f32x2 ----
    ull_t wu[16];   // W_hh[j][half*32 .. half*32+31]
    {
        const ulonglong2* wr = reinterpret_cast<const ulonglong2*>(W_hh + j * H + half * 32);
#pragma unroll
        for (int m = 0; m < 8; m++) { ulonglong2 v = wr[m]; wu[2*m] = v.x; wu[2*m+1] = v.y; }
    }
    ull_t iu[8];    // W_in[j][half*16 .. half*16+15]
    {
        const ulonglong2* wr = reinterpret_cast<const ulonglong2*>(W_in + j * D + half * 16);
#pragma unroll
        for (int m = 0; m < 4; m++) { ulonglong2 v = wr[m]; iu[2*m] = v.x; iu[2*m+1] = v.y; }
    }
    // bias folded into half0's accumulator init (removes a serial FADD after shfl)
    const float bias0 = (half == 0) ? (b_hh[j] + b_in[j]) : 0.0f;
    const float alpha = (float)(16.67 / 40.0);
    const float oma   = (float)(1.0 - 16.67 / 40.0);

    if (half == 0) hbuf[0][sb][j] = 0.0f;   // h0 = 0
    float hj = 0.0f;

    const int nchunk = (T + CH - 1) / CH;

    // ---- async x chunk loader: 128 threads/group copy CH*D*4 = 4KB (2x16B each) ----
    auto issue_chunk = [&](int c, int buf) {
        const size_t base_elem = ((size_t)bc * T + (size_t)c * CH) * D;
        const char* srcb = (const char*)(x + base_elem);
        uint32_t dstb = (uint32_t)__cvta_generic_to_shared(&xbuf[buf][sb][0]);
#pragma unroll
        for (int q = 0; q < 2; q++) {
            int off16 = r + 128 * q;          // 16B-unit index, 256 units per chunk
            int row   = off16 >> 3;           // 8 units per timestep row
            bool ok   = active && (c * CH + row) < T;
            const void* src = ok ? (const void*)(srcb + (size_t)off16 * 16)
                                 : (const void*)x;
            cp_async16(dstb + off16 * 16, src, ok ? 16 : 0);
        }
        cp_commit();
    };

    issue_chunk(0, 0);
    if (nchunk > 1) issue_chunk(1, 1); else cp_commit();

    int cur = 0;
    const size_t outbase = (size_t)bc * T * H + j;   // used by half==0 only

#define STEP_BODY(tt)                                                              \
    {                                                                              \
        const ulonglong2* hp = reinterpret_cast<const ulonglong2*>(                \
            &hbuf[cur][sb][half * 32]);                                            \
        const ulonglong2* xp = reinterpret_cast<const ulonglong2*>(                \
            &xbuf[xb][sb][(tt) * D + half * 16]);                                  \
        ull_t a0 = pack2(bias0, 0.0f);                                             \
        ull_t a1 = 0ull, a2 = 0ull, a3 = 0ull;                                     \
        const float leak = hj * oma;                                               \
        _Pragma("unroll")                                                          \
        for (int m = 0; m < 8; m++) {                                              \
            ulonglong2 hv = hp[m];                                                 \
            ffma2((m & 1) ? a1 : a0, wu[2 * m],     hv.x);                         \
            ffma2((m & 1) ? a3 : a2, wu[2 * m + 1], hv.y);                         \
        }                                                                          \
        _Pragma("unroll")                                                          \
        for (int m = 0; m < 4; m++) {                                              \
            ulonglong2 xv = xp[m];                                                 \
            ffma2((m & 1) ? a1 : a0, iu[2 * m],     xv.x);                         \
            ffma2((m & 1) ? a3 : a2, iu[2 * m + 1], xv.y);                         \
        }                                                                          \
        float p   = hsum2(add2(add2(a0, a1), add2(a2, a3)));                       \
        float tot = p + __shfl_xor_sync(0xffffffffu, p, 1);                        \
        float hnew = fmaxf(fmaf(tot, alpha, leak), 0.0f);                          \
        if (half == 0) {                                                           \
            hbuf[cur ^ 1][sb][j] = hnew;                                           \
            if (active) out[obase_c + (size_t)(tt) * H] = hnew;                    \
        }                                                                          \
        hj = hnew;                                                                 \
        cur ^= 1;                                                                  \
        group_bar(barid);                                                          \
    }

    for (int c = 0; c < nchunk; c++) {
        cp_wait1();            // this thread's chunk-c copies landed
        group_bar(barid);      // group-wide visibility of xbuf chunk c (+ hbuf)

        const int xb   = c & 1;
        const int tend = min(CH, T - c * CH);
        const size_t obase_c = outbase + (size_t)c * CH * H;

        if (tend == CH) {
#pragma unroll 4
            for (int tt = 0; tt < CH; tt++) STEP_BODY(tt)
        } else {
            for (int tt = 0; tt < tend; tt++) STEP_BODY(tt)
        }

        if (c + 2 < nchunk) issue_chunk(c + 2, xb); else cp_commit();
    }
#undef STEP_BODY

    // h_last appended after outputs
    if (active && half == 0) out[(size_t)B * T * H + (size_t)b * H + j] = hj;
}

extern "C" void kernel_launch(void* const* d_in, const int* in_sizes, int n_in,
                              void* d_out, int out_size)
{
    const float* x    = (const float*)d_in[0];
    // d_in[1] = seq_lengths: forward-dead (mask only gates gradients)
    const float* W_in = (const float*)d_in[2];
    const float* b_in = (const float*)d_in[3];
    const float* W_hh = (const float*)d_in[4];
    const float* b_hh = (const float*)d_in[5];
    float* out = (float*)d_out;

    const int B = in_sizes[1];
    const int H = in_sizes[5];
    const int D = in_sizes[2] / H;
    const long long T = (long long)in_sizes[0] / ((long long)B * D);

    const int grid = (B + 1) / 2;
    ctrnn_scan_kernel<<<grid, 256>>>(x, W_in, b_in, W_hh, b_hh, out, B, (int)T);
}

// round 4
// speedup vs baseline: 1.6935x; 1.5029x over previous
#include <cuda_runtime.h>
#include <cstdint>

typedef unsigned long long ull_t;

// ---- packed f32x2 helpers (Blackwell FFMA2 path) ----
__device__ __forceinline__ void ffma2(ull_t &acc, ull_t a, ull_t b) {
    asm volatile("fma.rn.f32x2 %0, %1, %2, %0;" : "+l"(acc) : "l"(a), "l"(b));
}
__device__ __forceinline__ ull_t add2(ull_t a, ull_t b) {
    ull_t r; asm("add.rn.f32x2 %0, %1, %2;" : "=l"(r) : "l"(a), "l"(b)); return r;
}
__device__ __forceinline__ float hsum2(ull_t v) {
    float lo, hi; asm("mov.b64 {%0,%1}, %2;" : "=f"(lo), "=f"(hi) : "l"(v));
    return lo + hi;
}
__device__ __forceinline__ ull_t pack2(float lo, float hi) {
    ull_t r; asm("mov.b64 %0, {%1, %2};" : "=l"(r) : "f"(lo), "f"(hi)); return r;
}
__device__ __forceinline__ ull_t mul2(ull_t a, ull_t b) {
    ull_t r; asm("mul.rn.f32x2 %0, %1, %2;" : "=l"(r) : "l"(a), "l"(b)); return r;
}

__device__ __forceinline__ void cp_async16(uint32_t dst, const void* src, int src_sz) {
    asm volatile("cp.async.cg.shared.global [%0], [%1], 16, %2;"
                 :: "r"(dst), "l"(src), "r"(src_sz));
}
__device__ __forceinline__ void cp_commit() {
    asm volatile("cp.async.commit_group;");
}
__device__ __forceinline__ void cp_wait1() {
    asm volatile("cp.async.wait_group 1;" ::: "memory");
}
// per-batch barrier over 64 threads (2 warps)
__device__ __forceinline__ void group_bar(int id) {
    asm volatile("bar.sync %0, 64;" :: "r"(id) : "memory");
}

// scratch for precomputed alpha*(x@W_in^T + b_in + b_hh): B=256, T=2048, H=64
#define XP_CAP (256u * 2048u * 64u)
__device__ float g_xp[XP_CAP];

// =====================================================================
// Pre-pass: xp[row, j] = alpha * (x[row,:]·W_in[j,:] + b_in[j] + b_hh[j])
// row = b*T + t; block = 256 thr handles 128 rows; thread = (j, rowgroup)
// =====================================================================
__global__ void __launch_bounds__(256, 4)
xproj_kernel(const float* __restrict__ x,
             const float* __restrict__ W_in,
             const float* __restrict__ b_in,
             const float* __restrict__ b_hh,
             int BT)
{
    constexpr int ROWS = 128;
    constexpr int D = 32;
    const float alpha = (float)(16.67 / 40.0);

    __shared__ __align__(16) float xs[ROWS * D];   // 16KB

    const int tid = threadIdx.x;
    const int j   = tid & 63;
    const int rg  = tid >> 6;
    const long long row0 = (long long)blockIdx.x * ROWS;

    // stage x tile: 128 rows * 32 f = 1024 x 16B units; 4 per thread
    {
        const float4* src = reinterpret_cast<const float4*>(x) + row0 * (D / 4);
        float4* dst = reinterpret_cast<float4*>(xs);
        const long long lim = (long long)BT * (D / 4);
#pragma unroll
        for (int q = 0; q < 4; q++) {
            int u = tid + 256 * q;
            float4 v = (row0 * (D / 4) + u < lim) ? src[u]
                                                  : make_float4(0.f, 0.f, 0.f, 0.f);
            dst[u] = v;
        }
    }
    __syncthreads();

    // W_in row j in packed registers
    ull_t wi[16];
    {
        const ulonglong2* wr = reinterpret_cast<const ulonglong2*>(W_in + j * D);
#pragma unroll
        for (int m = 0; m < 8; m++) { ulonglong2 v = wr[m]; wi[2*m] = v.x; wi[2*m+1] = v.y; }
    }
    const float ab = alpha * (b_in[j] + b_hh[j]);

#pragma unroll 4
    for (int rr = 0; rr < 32; rr++) {
        const int r = rg * 32 + rr;
        const long long row = row0 + r;
        if (row >= BT) break;
        const ulonglong2* xr = reinterpret_cast<const ulonglong2*>(&xs[r * D]);
        ull_t a0 = 0ull, a1 = 0ull, a2 = 0ull, a3 = 0ull;
#pragma unroll
        for (int m = 0; m < 8; m++) {
            ulonglong2 v = xr[m];
            ffma2((m & 1) ? a1 : a0, wi[2 * m],     v.x);
            ffma2((m & 1) ? a3 : a2, wi[2 * m + 1], v.y);
        }
        float dot = hsum2(add2(add2(a0, a1), add2(a2, a3)));
        g_xp[row * 64 + j] = fmaf(dot, alpha, ab);
    }
}

// =====================================================================
// Recurrence: h <- relu(oma*h + Wa·h + xp), Wa = alpha*W_hh in registers.
// Block = 128 thr = 2 independent batches (64 thr each, own named barrier).
// Thread = one output channel j. xp staged in CH-step chunks via cp.async.
// =====================================================================
__global__ void __launch_bounds__(128, 1)
ctrnn_scan_kernel(const float* __restrict__ W_hh,
                  float* __restrict__ out,
                  int B, int T)
{
    constexpr int H  = 64;
    constexpr int CH = 32;   // timesteps per xp-staging chunk

    const int tid = threadIdx.x;
    const int sb  = tid >> 6;        // batch slot (0/1)
    const int j   = tid & 63;        // channel
    const int barid = sb + 1;
    const int b   = blockIdx.x * 2 + sb;
    const bool active = (b < B);
    const int bc  = active ? b : (B - 1);

    __shared__ __align__(16) float hbuf[2][2][H];           // [ping][sb][H]
    __shared__ __align__(16) float xbuf[2][2][CH * H];      // [ping][sb][CH*H] (32KB)

    // Wa = alpha * W_hh[j] packed
    const float alpha = (float)(16.67 / 40.0);
    const float oma   = (float)(1.0 - 16.67 / 40.0);
    const ull_t alpha2 = pack2(alpha, alpha);
    ull_t wu[32];
    {
        const ulonglong2* wr = reinterpret_cast<const ulonglong2*>(W_hh + j * H);
#pragma unroll
        for (int m = 0; m < 16; m++) {
            ulonglong2 v = wr[m];
            wu[2 * m]     = mul2(v.x, alpha2);
            wu[2 * m + 1] = mul2(v.y, alpha2);
        }
    }

    hbuf[0][sb][j] = 0.0f;
    float hj = 0.0f;

    const int nchunk = (T + CH - 1) / CH;

    // xp chunk loader: CH*H*4 = 8KB = 512 x 16B units; 64 thr -> 8 each
    auto issue_chunk = [&](int c, int buf) {
        const float* src = g_xp + ((size_t)bc * T + (size_t)c * CH) * H;
        const char* srcb = (const char*)src;
        uint32_t dstb = (uint32_t)__cvta_generic_to_shared(&xbuf[buf][sb][0]);
#pragma unroll
        for (int q = 0; q < 8; q++) {
            int off16 = j + 64 * q;          // 512 units per chunk
            int row   = off16 >> 4;          // 16 units (256B) per timestep
            bool ok   = active && (c * CH + row) < T;
            const void* s = ok ? (const void*)(srcb + (size_t)off16 * 16)
                               : (const void*)g_xp;
            cp_async16(dstb + off16 * 16, s, ok ? 16 : 0);
        }
        cp_commit();
    };

    issue_chunk(0, 0);
    if (nchunk > 1) issue_chunk(1, 1); else cp_commit();

    int cur = 0;
    const size_t outbase = (size_t)bc * T * H + j;

#define STEP_BODY(tt)                                                              \
    {                                                                              \
        const ulonglong2* hp = reinterpret_cast<const ulonglong2*>(hbuf[cur][sb]); \
        const float xps = xbuf[xb][sb][(tt) * H + j];                              \
        ull_t a0 = pack2(xps, 0.0f);                                               \
        ull_t a1 = 0ull, a2 = 0ull, a3 = 0ull;                                     \
        _Pragma("unroll")                                                          \
        for (int m = 0; m < 16; m++) {                                             \
            ulonglong2 hv = hp[m];                                                 \
            ffma2((m & 1) ? a1 : a0, wu[2 * m],     hv.x);                         \
            ffma2((m & 1) ? a3 : a2, wu[2 * m + 1], hv.y);                         \
        }                                                                          \
        float p = hsum2(add2(add2(a0, a1), add2(a2, a3)));                         \
        float hnew = fmaxf(fmaf(hj, oma, p), 0.0f);                                \
        hbuf[cur ^ 1][sb][j] = hnew;                                               \
        if (active) out[obase_c + (size_t)(tt) * H] = hnew;                        \
        hj = hnew;                                                                 \
        cur ^= 1;                                                                  \
        group_bar(barid);                                                          \
    }

    for (int c = 0; c < nchunk; c++) {
        cp_wait1();            // this thread's chunk-c copies landed
        group_bar(barid);      // batch-wide visibility of xbuf chunk c (+ hbuf)

        const int xb   = c & 1;
        const int tend = min(CH, T - c * CH);
        const size_t obase_c = outbase + (size_t)c * CH * H;

        if (tend == CH) {
#pragma unroll 4
            for (int tt = 0; tt < CH; tt++) STEP_BODY(tt)
        } else {
            for (int tt = 0; tt < tend; tt++) STEP_BODY(tt)
        }

        if (c + 2 < nchunk) issue_chunk(c + 2, xb); else cp_commit();
    }
#undef STEP_BODY

    // h_last appended after outputs
    if (active) out[(size_t)B * T * H + (size_t)b * H + j] = hj;
}

extern "C" void kernel_launch(void* const* d_in, const int* in_sizes, int n_in,
                              void* d_out, int out_size)
{
    const float* x    = (const float*)d_in[0];
    // d_in[1] = seq_lengths: forward-dead (mask only gates gradients)
    const float* W_in = (const float*)d_in[2];
    const float* b_in = (const float*)d_in[3];
    const float* W_hh = (const float*)d_in[4];
    const float* b_hh = (const float*)d_in[5];
    float* out = (float*)d_out;

    const int B = in_sizes[1];
    const int H = in_sizes[5];
    const int D = in_sizes[2] / H;
    const long long T = (long long)in_sizes[0] / ((long long)B * D);
    const long long BT = (long long)B * T;

    // pre-pass: xp = alpha*(x@W_in^T + b_in + b_hh)
    const int pgrid = (int)((BT + 127) / 128);
    xproj_kernel<<<pgrid, 256>>>(x, W_in, b_in, b_hh, (int)BT);

    // recurrence
    const int grid = (B + 1) / 2;
    ctrnn_scan_kernel<<<grid, 128>>>(W_hh, out, B, (int)T);
}